// round 8
// baseline (speedup 1.0000x reference)
#include <cuda_runtime.h>

// LMNN loss on GB300 — R1 streaming body (measured optimum: 6.33 TB/s,
// 79.8% DRAM) with the init kernel fused away via a FENCE-FREE last-block
// reduction: release/acquire ordering comes from a single
// atom.acq_rel.gpu.inc on the ticket (L2-side, no CCTL.IVALL), unlike the
// __threadfence version (R6) whose membar.gl flushed L1D per finishing CTA
// and cost 6-8% DRAM throughput.
//
// outputs: [2048, 512, 128] f32, label_inds: [2048, 511] i32, out: scalar f32.

#define NSEG 2048
#define PPS  512
#define DDIM 128
#define NPTS 511   // PPS - 1
#define NTHR 256
#define NWRP 8

__device__ float    g_partial[NSEG];
__device__ unsigned g_ticket = 0;   // self-resets via inc-with-modulus wrap

__global__ __launch_bounds__(NTHR, 8)
void lmnn_kernel(const float* __restrict__ outputs,
                 const int*   __restrict__ labels,
                 float*       __restrict__ out)
{
    __shared__ float sh_d2[NPTS];
    __shared__ int   sh_same[NPTS];
    __shared__ float sh_red[NWRP];
    __shared__ int   sh_last;

    const int seg  = blockIdx.x;
    const int tid  = threadIdx.x;
    const int warp = tid >> 5;
    const int lane = tid & 31;

    // Row base for this segment, viewed as float4 (32 float4 per 128-f row).
    const float4* base = reinterpret_cast<const float4*>(
        outputs + (size_t)seg * PPS * DDIM);

    // Center row: lane l owns dims [4l, 4l+4). Redundant per-warp load; L1 hit.
    const float4 c = base[lane];

    // Same-label flags (vs label of point 0 of the 511).
    const int* lab = labels + (size_t)seg * NPTS;
    const int lab0 = lab[0];
    for (int j = tid; j < NPTS; j += NTHR)
        sh_same[j] = (lab[j] == lab0);

    // d2 for each point: warp w handles points w, w+8, w+16, ...
    #pragma unroll 4
    for (int j = warp; j < NPTS; j += NWRP) {
        const float4 p = base[(j + 1) * (DDIM / 4) + lane];
        const float dx = p.x - c.x;
        const float dy = p.y - c.y;
        const float dz = p.z - c.z;
        const float dw = p.w - c.w;
        float s = dx * dx + dy * dy + dz * dz + dw * dw;
        #pragma unroll
        for (int o = 16; o > 0; o >>= 1)
            s += __shfl_xor_sync(0xffffffffu, s, o);
        if (lane == 0) sh_d2[j] = s;
    }
    __syncthreads();

    // pull_d = min d2 over same-label points (j=0 is always same-label).
    float lmin = __int_as_float(0x7f800000);  // +inf
    for (int j = tid; j < NPTS; j += NTHR)
        if (sh_same[j]) lmin = fminf(lmin, sh_d2[j]);
    #pragma unroll
    for (int o = 16; o > 0; o >>= 1)
        lmin = fminf(lmin, __shfl_xor_sync(0xffffffffu, lmin, o));
    if (lane == 0) sh_red[warp] = lmin;
    __syncthreads();

    float pull = sh_red[0];
    #pragma unroll
    for (int w = 1; w < NWRP; w++) pull = fminf(pull, sh_red[w]);
    const float margin = 1.0f + pull;

    // push = sum over diff-label points of max(margin - d2, 0).
    float lsum = 0.0f;
    for (int j = tid; j < NPTS; j += NTHR)
        if (!sh_same[j]) lsum += fmaxf(margin - sh_d2[j], 0.0f);
    #pragma unroll
    for (int o = 16; o > 0; o >>= 1)
        lsum += __shfl_xor_sync(0xffffffffu, lsum, o);
    __syncthreads();          // all reads of sh_red (pull) done before reuse
    if (lane == 0) sh_red[warp] = lsum;
    __syncthreads();

    // Publish per-segment partial; last CTA reduces all of them into out.
    if (tid == 0) {
        float push = 0.0f;
        #pragma unroll
        for (int w = 0; w < NWRP; w++) push += sh_red[w];
        g_partial[seg] = pull + push;   // weak store; ordered by release below

        // Release-increment the ticket: orders the g_partial store before the
        // increment, and acquires all other CTAs' prior releases when we read
        // old == NSEG-1. No membar -> no CCTL.IVALL -> L1D of co-resident
        // streaming CTAs untouched. inc wraps to 0 at NSEG-1 (deterministic
        // initial state on every graph replay).
        unsigned old;
        asm volatile("atom.acq_rel.gpu.global.inc.u32 %0, [%1], %2;"
                     : "=r"(old)
                     : "l"(&g_ticket), "r"((unsigned)(NSEG - 1))
                     : "memory");
        sh_last = (old == NSEG - 1);
    }
    __syncthreads();

    if (sh_last) {
        float acc = 0.0f;
        const volatile float* vp = g_partial;  // strong loads, bypass L1
        for (int i = tid; i < NSEG; i += NTHR)
            acc += vp[i];
        #pragma unroll
        for (int o = 16; o > 0; o >>= 1)
            acc += __shfl_xor_sync(0xffffffffu, acc, o);
        if (lane == 0) sh_red[warp] = acc;
        __syncthreads();
        if (tid == 0) {
            float tot = 0.0f;
            #pragma unroll
            for (int w = 0; w < NWRP; w++) tot += sh_red[w];
            *out = tot / (float)((size_t)NSEG * PPS);
        }
    }
}

extern "C" void kernel_launch(void* const* d_in, const int* in_sizes, int n_in,
                              void* d_out, int out_size)
{
    const float* outputs = (const float*)d_in[0];
    const int*   labels  = (const int*)d_in[1];
    float*       out     = (float*)d_out;

    lmnn_kernel<<<NSEG, NTHR>>>(outputs, labels, out);
}

// round 9
// speedup vs baseline: 1.0977x; 1.0977x over previous
#include <cuda_runtime.h>

// LMNN loss on GB300 — R1 streaming body (measured ceiling: 6.33 TB/s) with a
// fence-free O(1) fused tail:
//   per-CTA:  relaxed red.add.f32 into g_accum  (same op class as R1's
//             atomicAdd tail, proven harmless to the stream)
//             + atom.RELEASE.inc ticket          (release only: orders the add,
//             no L1D invalidate — R6/R8 showed acquire/full-fence per CTA
//             costs 6-10% DRAM)
//   last CTA: ONE atom.acquire.exch(g_accum, 0)  (reads total, self-resets for
//             the next graph replay), then plain store to out. No O(NSEG)
//             serial reduce tail (that killed R6/R8), no init kernel (~1.9us
//             of R1/R7's total).
//
// outputs: [2048, 512, 128] f32, label_inds: [2048, 511] i32, out: scalar f32.

#define NSEG 2048
#define PPS  512
#define DDIM 128
#define NPTS 511   // PPS - 1
#define NTHR 256
#define NWRP 8

__device__ float    g_accum  = 0.0f;  // self-resets via exch(0) each replay
__device__ unsigned g_ticket = 0;     // self-resets via inc wrap

__global__ __launch_bounds__(NTHR, 8)
void lmnn_kernel(const float* __restrict__ outputs,
                 const int*   __restrict__ labels,
                 float*       __restrict__ out)
{
    __shared__ float sh_d2[NPTS];
    __shared__ int   sh_same[NPTS];
    __shared__ float sh_red[NWRP];

    const int seg  = blockIdx.x;
    const int tid  = threadIdx.x;
    const int warp = tid >> 5;
    const int lane = tid & 31;

    // Row base for this segment, viewed as float4 (32 float4 per 128-f row).
    const float4* base = reinterpret_cast<const float4*>(
        outputs + (size_t)seg * PPS * DDIM);

    // Center row: lane l owns dims [4l, 4l+4). Redundant per-warp load; L1 hit.
    const float4 c = base[lane];

    // Same-label flags (vs label of point 0 of the 511).
    const int* lab = labels + (size_t)seg * NPTS;
    const int lab0 = lab[0];
    for (int j = tid; j < NPTS; j += NTHR)
        sh_same[j] = (lab[j] == lab0);

    // d2 for each point: warp w handles points w, w+8, w+16, ...
    #pragma unroll 4
    for (int j = warp; j < NPTS; j += NWRP) {
        const float4 p = base[(j + 1) * (DDIM / 4) + lane];
        const float dx = p.x - c.x;
        const float dy = p.y - c.y;
        const float dz = p.z - c.z;
        const float dw = p.w - c.w;
        float s = dx * dx + dy * dy + dz * dz + dw * dw;
        #pragma unroll
        for (int o = 16; o > 0; o >>= 1)
            s += __shfl_xor_sync(0xffffffffu, s, o);
        if (lane == 0) sh_d2[j] = s;
    }
    __syncthreads();

    // pull_d = min d2 over same-label points (j=0 is always same-label).
    float lmin = __int_as_float(0x7f800000);  // +inf
    for (int j = tid; j < NPTS; j += NTHR)
        if (sh_same[j]) lmin = fminf(lmin, sh_d2[j]);
    #pragma unroll
    for (int o = 16; o > 0; o >>= 1)
        lmin = fminf(lmin, __shfl_xor_sync(0xffffffffu, lmin, o));
    if (lane == 0) sh_red[warp] = lmin;
    __syncthreads();

    float pull = sh_red[0];
    #pragma unroll
    for (int w = 1; w < NWRP; w++) pull = fminf(pull, sh_red[w]);
    const float margin = 1.0f + pull;

    // push = sum over diff-label points of max(margin - d2, 0).
    float lsum = 0.0f;
    for (int j = tid; j < NPTS; j += NTHR)
        if (!sh_same[j]) lsum += fmaxf(margin - sh_d2[j], 0.0f);
    #pragma unroll
    for (int o = 16; o > 0; o >>= 1)
        lsum += __shfl_xor_sync(0xffffffffu, lsum, o);
    __syncthreads();          // all reads of sh_red (pull) done before reuse
    if (lane == 0) sh_red[warp] = lsum;
    __syncthreads();

    if (tid == 0) {
        float push = 0.0f;
        #pragma unroll
        for (int w = 0; w < NWRP; w++) push += sh_red[w];
        const float part = pull + push;

        // Relaxed fire-and-forget add into the accumulator (L2-side REDG;
        // identical op class to R1's atomicAdd tail).
        asm volatile("red.relaxed.gpu.global.add.f32 [%0], %1;"
                     :: "l"(&g_accum), "f"(part) : "memory");

        // Release-increment the ticket: orders the add above before the inc.
        // Release only -> no L1D invalidation of co-resident streaming CTAs.
        // inc wraps to 0 at old==NSEG-1 (self-reset per graph replay).
        unsigned old;
        asm volatile("atom.release.gpu.global.inc.u32 %0, [%1], %2;"
                     : "=r"(old)
                     : "l"(&g_ticket), "r"((unsigned)(NSEG - 1))
                     : "memory");

        if (old == NSEG - 1) {
            // All 2047 other adds are L2-visible: add_i <rel inc_i <addr-order
            // inc_last <dep exch. Acquire-exchange reads the total AND resets
            // g_accum to 0 for the next replay. One acquire on the whole run.
            unsigned bits;
            asm volatile("atom.acquire.gpu.global.exch.b32 %0, [%1], %2;"
                         : "=r"(bits)
                         : "l"(&g_accum), "r"(0u)
                         : "memory");
            const float tot = __uint_as_float(bits);
            *out = tot / (float)((size_t)NSEG * PPS);
        }
    }
}

extern "C" void kernel_launch(void* const* d_in, const int* in_sizes, int n_in,
                              void* d_out, int out_size)
{
    const float* outputs = (const float*)d_in[0];
    const int*   labels  = (const int*)d_in[1];
    float*       out     = (float*)d_out;

    lmnn_kernel<<<NSEG, NTHR>>>(outputs, labels, out);
}

// round 10
// speedup vs baseline: 1.1147x; 1.0155x over previous
#include <cuda_runtime.h>

// LMNN loss on GB300 — FINAL (converged after 9 rounds).
// outputs: [2048, 512, 128] f32, label_inds: [2048, 511] i32, out: scalar f32.
//
// Streaming body = R1 schedule, the measured optimum (6.33 TB/s, 79.8% DRAM):
//   - one CTA per segment, 256 thr / 8 CTA/SM / 32 regs (occupancy-max;
//     128-thr single-wave and 48-reg batched variants were slower)
//   - warp-per-point: lane l holds float4 of dims [4l,4l+4) -> each 512B
//     point row is one coalesced LDG.128 per lane; unroll 4
//   - plain loads (__ldcs and cp.async.bulk both reduced achieved BW)
// Tail = fence-free O(1) fused reduction (saves the serialized init kernel):
//   - relaxed red.add.f32 into g_accum (L2-side, stream-harmless)
//   - atom.RELEASE.inc ticket (release only: per-CTA acquire/full-fence
//     variants flushed L1D under co-resident streaming CTAs, -6..10% DRAM)
//   - single last-CTA atom.acquire.exch reads the total AND zeroes g_accum
//     for the next graph replay (deterministic state each replay).

#define NSEG 2048
#define PPS  512
#define DDIM 128
#define NPTS 511   // PPS - 1
#define NTHR 256
#define NWRP 8

__device__ float    g_accum  = 0.0f;  // self-resets via exch(0) each replay
__device__ unsigned g_ticket = 0;     // self-resets via inc wrap

__global__ __launch_bounds__(NTHR, 8)
void lmnn_kernel(const float* __restrict__ outputs,
                 const int*   __restrict__ labels,
                 float*       __restrict__ out)
{
    __shared__ float sh_d2[NPTS];
    __shared__ int   sh_same[NPTS];
    __shared__ float sh_red[NWRP];

    const int seg  = blockIdx.x;
    const int tid  = threadIdx.x;
    const int warp = tid >> 5;
    const int lane = tid & 31;

    // Row base for this segment, viewed as float4 (32 float4 per 128-f row).
    const float4* base = reinterpret_cast<const float4*>(
        outputs + (size_t)seg * PPS * DDIM);

    // Center row: lane l owns dims [4l, 4l+4). Redundant per-warp load; L1 hit.
    const float4 c = base[lane];

    // Same-label flags (vs label of point 0 of the 511).
    const int* lab = labels + (size_t)seg * NPTS;
    const int lab0 = lab[0];
    for (int j = tid; j < NPTS; j += NTHR)
        sh_same[j] = (lab[j] == lab0);

    // d2 for each point: warp w handles points w, w+8, w+16, ...
    #pragma unroll 4
    for (int j = warp; j < NPTS; j += NWRP) {
        const float4 p = base[(j + 1) * (DDIM / 4) + lane];
        const float dx = p.x - c.x;
        const float dy = p.y - c.y;
        const float dz = p.z - c.z;
        const float dw = p.w - c.w;
        float s = dx * dx + dy * dy + dz * dz + dw * dw;
        #pragma unroll
        for (int o = 16; o > 0; o >>= 1)
            s += __shfl_xor_sync(0xffffffffu, s, o);
        if (lane == 0) sh_d2[j] = s;
    }
    __syncthreads();

    // pull_d = min d2 over same-label points (j=0 is always same-label).
    float lmin = __int_as_float(0x7f800000);  // +inf
    for (int j = tid; j < NPTS; j += NTHR)
        if (sh_same[j]) lmin = fminf(lmin, sh_d2[j]);
    #pragma unroll
    for (int o = 16; o > 0; o >>= 1)
        lmin = fminf(lmin, __shfl_xor_sync(0xffffffffu, lmin, o));
    if (lane == 0) sh_red[warp] = lmin;
    __syncthreads();

    float pull = sh_red[0];
    #pragma unroll
    for (int w = 1; w < NWRP; w++) pull = fminf(pull, sh_red[w]);
    const float margin = 1.0f + pull;

    // push = sum over diff-label points of max(margin - d2, 0).
    float lsum = 0.0f;
    for (int j = tid; j < NPTS; j += NTHR)
        if (!sh_same[j]) lsum += fmaxf(margin - sh_d2[j], 0.0f);
    #pragma unroll
    for (int o = 16; o > 0; o >>= 1)
        lsum += __shfl_xor_sync(0xffffffffu, lsum, o);
    __syncthreads();          // all reads of sh_red (pull) done before reuse
    if (lane == 0) sh_red[warp] = lsum;
    __syncthreads();

    if (tid == 0) {
        float push = 0.0f;
        #pragma unroll
        for (int w = 0; w < NWRP; w++) push += sh_red[w];
        const float part = pull + push;

        // Relaxed fire-and-forget add into the accumulator (L2-side REDG).
        asm volatile("red.relaxed.gpu.global.add.f32 [%0], %1;"
                     :: "l"(&g_accum), "f"(part) : "memory");

        // Release-increment the ticket: orders the add above before the inc.
        // Release only -> no L1D invalidation of co-resident streaming CTAs.
        // inc wraps to 0 at old==NSEG-1 (self-reset per graph replay).
        unsigned old;
        asm volatile("atom.release.gpu.global.inc.u32 %0, [%1], %2;"
                     : "=r"(old)
                     : "l"(&g_ticket), "r"((unsigned)(NSEG - 1))
                     : "memory");

        if (old == NSEG - 1) {
            // All 2047 other adds are L2-visible: add_i <rel inc_i, and this
            // CTA's acquire pairs with those releases. Exchange reads the
            // total AND resets g_accum to 0 for the next replay.
            unsigned bits;
            asm volatile("atom.acquire.gpu.global.exch.b32 %0, [%1], %2;"
                         : "=r"(bits)
                         : "l"(&g_accum), "r"(0u)
                         : "memory");
            const float tot = __uint_as_float(bits);
            *out = tot / (float)((size_t)NSEG * PPS);
        }
    }
}

extern "C" void kernel_launch(void* const* d_in, const int* in_sizes, int n_in,
                              void* d_out, int out_size)
{
    const float* outputs = (const float*)d_in[0];
    const int*   labels  = (const int*)d_in[1];
    float*       out     = (float*)d_out;

    lmnn_kernel<<<NSEG, NTHR>>>(outputs, labels, out);
}